// round 6
// baseline (speedup 1.0000x reference)
#include <cuda_runtime.h>

#define NI 16384          // inputs per batch row
#define ND 65536          // detectors
#define KK 32             // members per detector (== warp size)
#define BB 32             // batch
#define NCHUNK 16         // detector chunks
#define DET_PER_CTA (ND / NCHUNK)   // 4096
#define THREADS 1024
#define WARPS (THREADS / 32)        // 32
#define DET_PER_WARP (DET_PER_CTA / WARPS)  // 128
#define NWORD (NI / 4)              // 4096 packed-byte counter words
#define SMEM_BYTES (NI * 4 + NWORD * 4)     // 64KB x-row + 16KB W = 80KB

// Per-chunk membership multiplicity, packed 4 u8 counts per u32 word.
// Batch-independent; rebuilt every kernel_launch call (zeroed in init).
__device__ unsigned g_M[NCHUNK][NWORD];

__global__ void init_kernel(float4* __restrict__ out) {
    int i = blockIdx.x * blockDim.x + threadIdx.x;   // BB*NI/4 = 131072 thr
    out[i] = make_float4(1.0f, 1.0f, 1.0f, 1.0f);
    if (i < NCHUNK * NWORD)
        ((unsigned*)g_M)[i] = 0u;
}

// Histogram: for each (detector, slot) entry, bump M[chunk][id] (packed byte).
// Spread gmem red.add — one pass over the 2M-entry table, once per launch.
__global__ void count_kernel(const int* __restrict__ det) {
    int idx = blockIdx.x * blockDim.x + threadIdx.x;   // [0, ND*KK)
    int id = __ldg(det + idx);
    int chunk = idx >> 17;                             // (idx/32)/4096
    atomicAdd(&g_M[chunk][id >> 2], 1u << ((id & 3) * 8));
}

// Order-preserving float -> unsigned key: x >= y (as floats) iff
// key(x) >= key(y) as unsigned. Equal floats -> equal keys.
__device__ __forceinline__ unsigned f32_order_key(unsigned u) {
    return u ^ (((int)u >> 31) | 0x80000000u);
}

__global__ void __launch_bounds__(THREADS, 2) inhibit_kernel(
    const float* __restrict__ x,
    const int*   __restrict__ det,
    float*       __restrict__ out)
{
    extern __shared__ unsigned char smem[];
    float*    xs = (float*)smem;                 // 64KB: x row
    unsigned* W  = (unsigned*)(smem + NI * 4);   // 16KB: packed winner counts

    const int tid   = threadIdx.x;
    const int chunk = blockIdx.x;               // 0..15
    const int b     = blockIdx.y;               // 0..31

    // Prologue: load x row (coalesced float4), zero W counters.
    const float4* xrow = (const float4*)(x + (size_t)b * NI);
    float4* xs4 = (float4*)xs;
    #pragma unroll
    for (int i = tid; i < NI / 4; i += THREADS)
        xs4[i] = xrow[i];
    #pragma unroll
    for (int i = tid; i < NWORD; i += THREADS)
        W[i] = 0u;
    __syncthreads();

    const int lane = tid & 31;
    const int warp = tid >> 5;
    const unsigned lt_mask = (1u << lane) - 1u;

    // Warp w owns DET_PER_WARP consecutive detectors; one detector row
    // == 128B == exactly one coalesced warp load.
    const int* dbase = det
        + ((size_t)(chunk * DET_PER_CTA + warp * DET_PER_WARP)) * KK + lane;

    #pragma unroll 4
    for (int i = 0; i < DET_PER_WARP; i++) {
        int id = __ldg(dbase + i * KK);
        unsigned key = f32_order_key(__float_as_uint(xs[id]));  // SMEM gather
        unsigned mkey = __reduce_max_sync(0xffffffffu, key);
        unsigned bal = __ballot_sync(0xffffffffu, key == mkey);
        // winner = lowest lane achieving max (matches jnp.argmax tie-break).
        // Only that single lane issues the atomic: ~1 smem atomic per
        // detector instead of 31 loser STS marks.
        if (key == mkey && (bal & lt_mask) == 0u)
            atomicAdd(&W[id >> 2], 1u << ((id & 3) * 8));
    }
    __syncthreads();

    // Flush: input i inhibited by this chunk iff wins != memberships.
    // All byte counts < 256, so word equality == 4-byte equality (no carry).
    const unsigned* Mrow = g_M[chunk];
    float* orow = out + (size_t)b * NI;
    #pragma unroll
    for (int i = tid; i < NWORD; i += THREADS) {
        unsigned w = W[i];
        unsigned m = __ldg(Mrow + i);
        if (w != m) {
            #pragma unroll
            for (int k = 0; k < 4; k++)
                if (((w >> (k * 8)) & 0xFFu) != ((m >> (k * 8)) & 0xFFu))
                    orow[4 * i + k] = 0.0f;
        }
    }
}

extern "C" void kernel_launch(void* const* d_in, const int* in_sizes, int n_in,
                              void* d_out, int out_size) {
    const float* x   = (const float*)d_in[0];   // [32, 16384] f32
    const int*   det = (const int*)d_in[1];     // [65536, 32] i32
    float*       out = (float*)d_out;           // [32, 16384] f32

    (void)in_sizes; (void)n_in; (void)out_size;

    cudaFuncSetAttribute(inhibit_kernel,
                         cudaFuncAttributeMaxDynamicSharedMemorySize,
                         SMEM_BYTES);

    // 1) out = 1.0 everywhere; M counters = 0.
    init_kernel<<<(BB * NI / 4) / 256, 256>>>((float4*)out);
    // 2) Build per-chunk membership histogram (batch-independent).
    count_kernel<<<(ND * KK) / 256, 256>>>(det);
    // 3) Winner-count per (chunk, batch); zero out where W != M.
    dim3 grid(NCHUNK, BB);
    inhibit_kernel<<<grid, THREADS, SMEM_BYTES>>>(x, det, out);
}

// round 7
// speedup vs baseline: 1.0863x; 1.0863x over previous
#include <cuda_runtime.h>

#define NI 16384          // inputs per batch row
#define ND 65536          // detectors
#define KK 32             // members per detector (== warp size)
#define BB 32             // batch
#define NCHUNK 16         // detector tiles
#define DET_PER_CTA (ND / NCHUNK)   // 4096
#define THREADS 1024
#define WARPS (THREADS / 32)        // 32
#define DET_PER_WARP (DET_PER_CTA / WARPS)  // 128
#define SMEM_BYTES (NI * 4)         // 64KB: x row only

// Global scratch (allocation-free rule: __device__ globals).
// g_M[i]      : membership multiplicity of input i over ALL detectors.
// g_W[b*NI+i] : number of detector wins of input i in batch b.
// spike(b,i) <=> g_W == g_M  (each detector contributes K slots: 1 winner,
// K-1 losers; so stat = M - W and stat==0 <=> W==M).
__device__ unsigned g_M[NI];
__device__ unsigned g_W[BB * NI];

__global__ void zero_kernel() {
    int i = blockIdx.x * blockDim.x + threadIdx.x;   // covers (BB+1)*NI
    if (i < NI) g_M[i] = 0u;
    else        g_W[i - NI] = 0u;
}

// M histogram: one RED.ADD per (detector, slot) entry. Batch-independent.
__global__ void count_kernel(const int* __restrict__ det) {
    int idx = blockIdx.x * blockDim.x + threadIdx.x;   // [0, ND*KK)
    atomicAdd(&g_M[__ldg(det + idx)], 1u);             // compiles to REDG
}

// Order-preserving float -> unsigned key: x >= y (as floats) iff
// key(x) >= key(y) as unsigned. Equal floats -> equal keys.
__device__ __forceinline__ unsigned f32_order_key(unsigned u) {
    return u ^ (((int)u >> 31) | 0x80000000u);
}

__global__ void __launch_bounds__(THREADS, 2) winner_kernel(
    const float* __restrict__ x,
    const int*   __restrict__ det)
{
    extern __shared__ float xs[];                // 64KB: x row for this batch

    const int tid   = threadIdx.x;
    const int chunk = blockIdx.x;               // 0..15
    const int b     = blockIdx.y;               // 0..31

    // Prologue: load x row into SMEM (coalesced float4).
    const float4* xrow = (const float4*)(x + (size_t)b * NI);
    float4* xs4 = (float4*)xs;
    #pragma unroll
    for (int i = tid; i < NI / 4; i += THREADS)
        xs4[i] = xrow[i];
    __syncthreads();

    const int lane = tid & 31;
    const int warp = tid >> 5;
    const unsigned lt_mask = (1u << lane) - 1u;
    unsigned* Wrow = g_W + (size_t)b * NI;

    // Warp w owns DET_PER_WARP consecutive detectors; one detector row
    // == 128B == exactly one coalesced warp load.
    const int* dbase = det
        + ((size_t)(chunk * DET_PER_CTA + warp * DET_PER_WARP)) * KK + lane;

    #pragma unroll 4
    for (int i = 0; i < DET_PER_WARP; i++) {
        int id = __ldg(dbase + i * KK);
        unsigned key = f32_order_key(__float_as_uint(xs[id]));  // SMEM gather
        unsigned mkey = __reduce_max_sync(0xffffffffu, key);
        unsigned bal = __ballot_sync(0xffffffffu, key == mkey);
        // winner = lowest lane achieving max (matches jnp.argmax tie-break).
        // Fire-and-forget gmem RED.ADD from that one lane — no smem atomics.
        if (key == mkey && (bal & lt_mask) == 0u)
            atomicAdd(Wrow + id, 1u);                // REDG (result unused)
    }
}

__global__ void finalize_kernel(float* __restrict__ out) {
    int idx = blockIdx.x * blockDim.x + threadIdx.x;   // [0, BB*NI)
    unsigned w = g_W[idx];
    unsigned m = g_M[idx & (NI - 1)];
    out[idx] = (w == m) ? 1.0f : 0.0f;
}

extern "C" void kernel_launch(void* const* d_in, const int* in_sizes, int n_in,
                              void* d_out, int out_size) {
    const float* x   = (const float*)d_in[0];   // [32, 16384] f32
    const int*   det = (const int*)d_in[1];     // [65536, 32] i32
    float*       out = (float*)d_out;           // [32, 16384] f32

    (void)in_sizes; (void)n_in; (void)out_size;

    cudaFuncSetAttribute(winner_kernel,
                         cudaFuncAttributeMaxDynamicSharedMemorySize,
                         SMEM_BYTES);

    // 1) Zero M and W counters.
    zero_kernel<<<((BB + 1) * NI) / 256, 256>>>();
    // 2) Membership histogram (batch-independent, rebuilt every call).
    count_kernel<<<(ND * KK) / 256, 256>>>(det);
    // 3) Winner counting per (chunk, batch) tile.
    dim3 grid(NCHUNK, BB);
    winner_kernel<<<grid, THREADS, SMEM_BYTES>>>(x, det);
    // 4) spike = (wins == memberships).
    finalize_kernel<<<(BB * NI) / 256, 256>>>(out);
}

// round 8
// speedup vs baseline: 1.1889x; 1.0944x over previous
#include <cuda_runtime.h>

#define NI 16384          // inputs per batch row
#define ND 65536          // detectors
#define KK 32             // members per detector (== warp size)
#define BB 32             // batch
#define NCHUNK 32         // detector tiles
#define DET_PER_CTA (ND / NCHUNK)   // 2048
#define THREADS 1024
#define WARPS (THREADS / 32)        // 32
#define DET_PER_WARP (DET_PER_CTA / WARPS)  // 64
#define SMEM_BYTES (NI * 8)         // 128KB: float2 {xA, xB} per input

// Global scratch (allocation-free rule: __device__ globals).
// g_M[i]      : membership multiplicity of input i over ALL detectors.
// g_W[b*NI+i] : number of detector wins of input i in batch b.
// spike(b,i) <=> W == M  (each detector: 1 winner slot, K-1 loser slots;
// stat = M - W, spike iff stat == 0). Duplicate ids / exact ties preserved:
// winner = lowest max slot, duplicates inflate M but not W -> inhibited,
// matching jnp.argmax semantics. Verified rel_err=0.0 in R6/R7.
__device__ unsigned g_M[NI];
__device__ unsigned g_W[BB * NI];

__global__ void zero_kernel() {
    int i = blockIdx.x * blockDim.x + threadIdx.x;   // covers (BB+1)*NI
    if (i < NI) g_M[i] = 0u;
    else        g_W[i - NI] = 0u;
}

// M histogram: one fire-and-forget RED.ADD per (detector, slot) entry.
__global__ void count_kernel(const int* __restrict__ det) {
    int idx = blockIdx.x * blockDim.x + threadIdx.x;   // [0, ND*KK)
    atomicAdd(&g_M[__ldg(det + idx)], 1u);             // REDG
}

// Order-preserving float -> unsigned key: x >= y (as floats) iff
// key(x) >= key(y) as unsigned. Equal floats -> equal keys.
__device__ __forceinline__ unsigned f32_order_key(unsigned u) {
    return u ^ (((int)u >> 31) | 0x80000000u);
}

// One CTA = one detector tile x one PAIR of batch rows. The LDS.64 gather
// and the det LDG are shared between the two batches.
__global__ void __launch_bounds__(THREADS, 1) winner_kernel(
    const float* __restrict__ x,
    const int*   __restrict__ det)
{
    extern __shared__ float2 xs2[];              // 128KB: {x_b0, x_b1}

    const int tid   = threadIdx.x;
    const int chunk = blockIdx.x;               // 0..31
    const int pair  = blockIdx.y;               // 0..15
    const int b0    = pair * 2;

    // Prologue: interleave two batch rows into smem (coalesced loads).
    const float* rowA = x + (size_t)b0 * NI;
    const float* rowB = rowA + NI;
    #pragma unroll
    for (int i = tid; i < NI; i += THREADS)
        xs2[i] = make_float2(__ldg(rowA + i), __ldg(rowB + i));
    __syncthreads();

    const int lane = tid & 31;
    const int warp = tid >> 5;
    const unsigned lt_mask = (1u << lane) - 1u;
    unsigned* WA = g_W + (size_t)b0 * NI;
    unsigned* WB = WA + NI;

    // Warp w owns DET_PER_WARP consecutive detectors; one detector row
    // == 128B == exactly one coalesced warp load.
    const int* dbase = det
        + ((size_t)(chunk * DET_PER_CTA + warp * DET_PER_WARP)) * KK + lane;

    #pragma unroll 4
    for (int i = 0; i < DET_PER_WARP; i++) {
        int id = __ldg(dbase + i * KK);
        float2 v = xs2[id];                          // LDS.64: both batches
        unsigned keyA = f32_order_key(__float_as_uint(v.x));
        unsigned keyB = f32_order_key(__float_as_uint(v.y));
        unsigned mA = __reduce_max_sync(0xffffffffu, keyA);
        unsigned mB = __reduce_max_sync(0xffffffffu, keyB);
        unsigned balA = __ballot_sync(0xffffffffu, keyA == mA);
        unsigned balB = __ballot_sync(0xffffffffu, keyB == mB);
        // winner = lowest lane achieving max (jnp.argmax tie-break);
        // that single lane fires one gmem RED.ADD (no return, no smem).
        if (keyA == mA && (balA & lt_mask) == 0u)
            atomicAdd(WA + id, 1u);
        if (keyB == mB && (balB & lt_mask) == 0u)
            atomicAdd(WB + id, 1u);
    }
}

__global__ void finalize_kernel(float* __restrict__ out) {
    int idx = blockIdx.x * blockDim.x + threadIdx.x;   // [0, BB*NI)
    out[idx] = (g_W[idx] == g_M[idx & (NI - 1)]) ? 1.0f : 0.0f;
}

extern "C" void kernel_launch(void* const* d_in, const int* in_sizes, int n_in,
                              void* d_out, int out_size) {
    const float* x   = (const float*)d_in[0];   // [32, 16384] f32
    const int*   det = (const int*)d_in[1];     // [65536, 32] i32
    float*       out = (float*)d_out;           // [32, 16384] f32

    (void)in_sizes; (void)n_in; (void)out_size;

    cudaFuncSetAttribute(winner_kernel,
                         cudaFuncAttributeMaxDynamicSharedMemorySize,
                         SMEM_BYTES);

    // 1) Zero M and W counters.
    zero_kernel<<<((BB + 1) * NI + 255) / 256, 256>>>();
    // 2) Membership histogram (batch-independent, rebuilt every call).
    count_kernel<<<(ND * KK) / 256, 256>>>(det);
    // 3) Winner counting: detector tile x batch-pair.
    dim3 grid(NCHUNK, BB / 2);
    winner_kernel<<<grid, THREADS, SMEM_BYTES>>>(x, det);
    // 4) spike = (wins == memberships).
    finalize_kernel<<<(BB * NI) / 256, 256>>>(out);
}